// round 15
// baseline (speedup 1.0000x reference)
#include <cuda_runtime.h>
#include <cuda_fp16.h>

#define NT 256
#define L_IN 4096
#define DZV 30
#define CV 10
#define B_TOT 512

typedef unsigned long long u64;

__constant__ float cWh[DZV*80];   // [d][c][j]
__constant__ float cZ[DZV];

// per-net block of 408 u64, all weights pre-duplicated (w,w):
// [0..96)    conv1: ch*12 + k*4 + oc      (ch<8, k<3, oc<4)
// [96..192)  conv2: 96 + ch*24 + k*8 + oc (ch<4, k<3, oc<8)
// [192..384) conv3: 192 + ch*24 + k*8 + oc (ch<8)
// [384..388) b1d, [388..396) b2d, [396..404) b3d, pad 408
__device__ u64 g_wdup[DZV*408];

__device__ __forceinline__ u64 f2u(float a, float b) {
    union { float2 f; u64 u; } c; c.f = make_float2(a, b); return c.u;
}
__device__ __forceinline__ float2 u2f(u64 v) {
    union { float2 f; u64 u; } c; c.u = v; return c.f;
}
__device__ __forceinline__ u64 ffma2(u64 a, u64 b, u64 c) {
    u64 d; asm("fma.rn.f32x2 %0, %1, %2, %3;" : "=l"(d) : "l"(a), "l"(b), "l"(c)); return d;
}
__device__ __forceinline__ void tap4(u64* acc, u64 t, ulonglong2 wa, ulonglong2 wb) {
    acc[0] = ffma2(wa.x, t, acc[0]);
    acc[1] = ffma2(wa.y, t, acc[1]);
    acc[2] = ffma2(wb.x, t, acc[2]);
    acc[3] = ffma2(wb.y, t, acc[3]);
}

__global__ void prep_kernel(const float* __restrict__ W1, const float* __restrict__ b1,
                            const float* __restrict__ W2, const float* __restrict__ b2,
                            const float* __restrict__ W3, const float* __restrict__ b3,
                            const float* __restrict__ z,  const float* __restrict__ bh,
                            float* __restrict__ out) {
    int i = blockIdx.x * blockDim.x + threadIdx.x;
    if (i < DZV*404) {
        int n = i / 404, r = i % 404;
        float v;
        if (r < 96) {
            int ch = r / 12, k = (r % 12) / 4, oc = r & 3;
            v = W1[n*96 + oc*24 + ch*3 + k];
        } else if (r < 192) {
            int t = r - 96, ch = t / 24, k = (t % 24) / 8, oc = t & 7;
            v = W2[n*96 + oc*12 + ch*3 + k];
        } else if (r < 384) {
            int t = r - 192, ch = t / 24, k = (t % 24) / 8, oc = t & 7;
            v = W3[n*192 + oc*24 + ch*3 + k];
        } else if (r < 388) v = b1[n*4 + (r-384)];
        else if (r < 396)   v = b2[n*8 + (r-388)];
        else                v = b3[n*8 + (r-396)];
        g_wdup[n*408 + r] = f2u(v, v);
    }
    if (i < B_TOT*CV) {
        int c = i % CV;
        float s = 0.f;
        #pragma unroll
        for (int d = 0; d < DZV; d++) s = fmaf(z[d], bh[d*CV + c], s);
        out[i] = s;
    }
}

// ---- smem layout ----
// XS (fp16): x[pos] at half index ch*CH_STR + (pos&7)*C_STR + (pos>>3)
#define C_STR    516
#define CH_STR   (8*C_STR)    // 4128 halfs
#define RED_OFF  16512        // up to 8 nets x 64 floats
#define HAL1_OFF 17024        // 8 warps x 4
#define HAL2_OFF 17056        // 8 warps x 16
#define WS_OFF   17184        // 2 x 816 floats (16B aligned: 17184*4 % 16 == 0)
#define SMEM_FLOATS 18816     // 75264 B -> 3 CTAs/SM (225792 <= 228KB)

__global__ __launch_bounds__(NT, 3)
void ensemble_kernel(const int* __restrict__ ids,
                     const float* __restrict__ mask,
                     const float* __restrict__ embed,
                     float* __restrict__ out)
{
    extern __shared__ float sm[];
    __half* smh = (__half*)sm;
    float* red  = sm + RED_OFF;
    float* hal1 = sm + HAL1_OFF;
    float* hal2 = sm + HAL2_OFF;

    const int tid  = threadIdx.x;
    const int lane = tid & 31;
    const int warp = tid >> 5;
    const int b    = blockIdx.x;
    const int g    = blockIdx.y;
    const int base_net = g * 5;       // 6 groups of 5 nets
    const int nets     = 5;

    // ---- zero pads XS[ch][c][512..515] (one slot per thread) ----
    {
        int ch = tid >> 5, c = (tid >> 2) & 7, j = tid & 3;
        smh[ch*CH_STR + c*C_STR + 512 + j] = __float2half_rn(0.f);
    }

    // ---- stage first net's weight block into buffer 0 ----
    if (tid < 204)
        ((float4*)(sm + WS_OFF))[tid] =
            __ldg((const float4*)g_wdup + (size_t)base_net*204 + tid);

    // ---- gather masked embeddings -> fp16, mod-8 deinterleaved ----
    #pragma unroll 1
    for (int i = tid; i < L_IN; i += NT) {
        int   id = __ldg(&ids[b*L_IN + i]);
        float m  = __ldg(&mask[b*L_IN + i]);
        float4 e0 = __ldg((const float4*)(embed + (size_t)id*8));
        float4 e1 = __ldg((const float4*)(embed + (size_t)id*8 + 4));
        __half* bp = smh + (i & 7)*C_STR + (i >> 3);
        bp[0*CH_STR] = __float2half_rn(e0.x*m);
        bp[1*CH_STR] = __float2half_rn(e0.y*m);
        bp[2*CH_STR] = __float2half_rn(e0.z*m);
        bp[3*CH_STR] = __float2half_rn(e0.w*m);
        bp[4*CH_STR] = __float2half_rn(e1.x*m);
        bp[5*CH_STR] = __float2half_rn(e1.y*m);
        bp[6*CH_STR] = __float2half_rn(e1.z*m);
        bp[7*CH_STR] = __float2half_rn(e1.w*m);
    }
    __syncthreads();

    float oacc = 0.f;

    #pragma unroll 1
    for (int dn = 0; dn < nets; dn++) {
        const int d = base_net + dn;
        const ulonglong2* WQ = (const ulonglong2*)(sm + WS_OFF + (dn & 1)*816);

        // ======== conv1: K3 S2, 8->4ch. thread owns r = 8t..8t+7 as
        //          pairs PJ[oc][j] = (h1[8t+j], h1[8t+4+j]), j<4 ========
        u64 A1[4][4];   // [j][oc]
        {
            ulonglong2 B0 = WQ[192], B1 = WQ[193];
            #pragma unroll
            for (int j = 0; j < 4; j++) {
                A1[j][0] = B0.x; A1[j][1] = B0.y;
                A1[j][2] = B1.x; A1[j][3] = B1.y;
            }
        }
        #pragma unroll 2
        for (int ch = 0; ch < 8; ch++) {
            const __half2* Xc = ((const __half2*)smh) + ch*(CH_STR/2) + tid;
            float2 F[8];
            #pragma unroll
            for (int m = 0; m < 8; m++)
                F[m] = __half22float2(Xc[m*(C_STR/2)]);
            float2 Fe = __half22float2(Xc[1]);
            u64 P[9];
            #pragma unroll
            for (int m = 0; m < 8; m++) P[m] = f2u(F[m].x, F[m].y);
            P[8] = f2u(F[0].y, Fe.x);
            ulonglong2 w00 = WQ[ch*6+0], w01 = WQ[ch*6+1];
            ulonglong2 w10 = WQ[ch*6+2], w11 = WQ[ch*6+3];
            ulonglong2 w20 = WQ[ch*6+4], w21 = WQ[ch*6+5];
            #pragma unroll
            for (int j = 0; j < 4; j++) {
                tap4(A1[j], P[2*j+0], w00, w01);
                tap4(A1[j], P[2*j+1], w10, w11);
                tap4(A1[j], P[2*j+2], w20, w21);
            }
        }
        // ReLU -> PJ[ch(=conv1 oc)][j]: stride-4 h1 pairs, register-resident
        u64 PJ[4][4];
        #pragma unroll
        for (int oc = 0; oc < 4; oc++)
            #pragma unroll
            for (int j = 0; j < 4; j++) {
                float2 p = u2f(A1[j][oc]);
                PJ[oc][j] = f2u(fmaxf(p.x, 0.f), fmaxf(p.y, 0.f));
            }

        // halo post: lane0 posts h1[8t] (lo of PJ[ch][0]) for left neighbor
        if (lane == 0) {
            #pragma unroll
            for (int ch = 0; ch < 4; ch++)
                hal1[warp*4 + ch] = u2f(PJ[ch][0]).x;
        }
        __syncthreads();                                  // B1

        // prefetch NEXT net's weights (buffer last read in net dn-1's conv3,
        // fully ordered before this B1)
        if (dn + 1 < nets && tid < 204)
            ((float4*)(sm + WS_OFF + ((dn+1) & 1)*816))[tid] =
                __ldg((const float4*)g_wdup + (size_t)(d+1)*204 + tid);

        float hxlo[4];
        #pragma unroll
        for (int ch = 0; ch < 4; ch++)
            hxlo[ch] = __shfl_down_sync(0xFFFFFFFFu, u2f(PJ[ch][0]).x, 1);
        if (lane == 31 && warp < 7) {
            #pragma unroll
            for (int ch = 0; ch < 4; ch++)
                hxlo[ch] = hal1[(warp+1)*4 + ch];
        }
        // t=255: hxlo garbage -> feeds only dead q=1023 (masked downstream)

        // ======== conv2: K3 S2, 4->8ch, oc-halved for registers.
        //          q pairs QI[oc][i] = (h2[4t+i], h2[4t+2+i]), i<2 ========
        u64 QI[8][2];
        #pragma unroll
        for (int h = 0; h < 2; h++) {
            u64 A2[2][4];
            {
                ulonglong2 Ba = WQ[194 + 2*h], Bb = WQ[195 + 2*h];
                #pragma unroll
                for (int i = 0; i < 2; i++) {
                    A2[i][0]=Ba.x; A2[i][1]=Ba.y; A2[i][2]=Bb.x; A2[i][3]=Bb.y;
                }
            }
            #pragma unroll
            for (int ch = 0; ch < 4; ch++) {
                const ulonglong2* wp = WQ + 48 + ch*12 + 2*h;
                ulonglong2 k0a = wp[0], k0b = wp[1];
                ulonglong2 k1a = wp[4], k1b = wp[5];
                ulonglong2 k2a = wp[8], k2b = wp[9];
                u64 HX = f2u(u2f(PJ[ch][0]).y, hxlo[ch]);   // h1 pair @ 8t+4
                tap4(A2[0], PJ[ch][0], k0a, k0b);
                tap4(A2[0], PJ[ch][1], k1a, k1b);
                tap4(A2[0], PJ[ch][2], k2a, k2b);
                tap4(A2[1], PJ[ch][2], k0a, k0b);
                tap4(A2[1], PJ[ch][3], k1a, k1b);
                tap4(A2[1], HX,        k2a, k2b);
            }
            #pragma unroll
            for (int jj = 0; jj < 4; jj++)
                #pragma unroll
                for (int i = 0; i < 2; i++) {
                    float2 p = u2f(A2[i][jj]);
                    QI[4*h + jj][i] = f2u(fmaxf(p.x, 0.f), fmaxf(p.y, 0.f));
                }
        }

        // halo post: lane0 posts h2[4t], h2[4t+1] (lo of each pair)
        if (lane == 0) {
            #pragma unroll
            for (int ch = 0; ch < 8; ch++) {
                hal2[warp*16 + ch]     = u2f(QI[ch][0]).x;
                hal2[warp*16 + 8 + ch] = u2f(QI[ch][1]).x;
            }
        }
        __syncthreads();                                  // B2

        float h2lo0[8], h2lo1[8];
        #pragma unroll
        for (int ch = 0; ch < 8; ch++) {
            h2lo0[ch] = __shfl_down_sync(0xFFFFFFFFu, u2f(QI[ch][0]).x, 1);
            h2lo1[ch] = __shfl_down_sync(0xFFFFFFFFu, u2f(QI[ch][1]).x, 1);
        }
        if (lane == 31 && warp < 7) {
            #pragma unroll
            for (int ch = 0; ch < 8; ch++) {
                h2lo0[ch] = hal2[(warp+1)*16 + ch];
                h2lo1[ch] = hal2[(warp+1)*16 + 8 + ch];
            }
        }

        // ======== conv3: K3 S1, 8->8ch, ReLU + pool, oc-halved.
        //          pairs (4t, 4t+2) and (4t+1, 4t+3); valid p < 1021 ========
        float psum[8];
        #pragma unroll
        for (int i = 0; i < 8; i++) psum[i] = 0.f;
        #pragma unroll
        for (int h = 0; h < 2; h++) {
            u64 A3[2][4];
            {
                ulonglong2 Ba = WQ[198 + 2*h], Bb = WQ[199 + 2*h];
                #pragma unroll
                for (int i = 0; i < 2; i++) {
                    A3[i][0]=Ba.x; A3[i][1]=Ba.y; A3[i][2]=Bb.x; A3[i][3]=Bb.y;
                }
            }
            #pragma unroll 2
            for (int ch = 0; ch < 8; ch++) {
                const ulonglong2* wp = WQ + 96 + ch*12 + 2*h;
                ulonglong2 k0a = wp[0], k0b = wp[1];
                ulonglong2 k1a = wp[4], k1b = wp[5];
                ulonglong2 k2a = wp[8], k2b = wp[9];
                u64 H0 = f2u(u2f(QI[ch][0]).y, h2lo0[ch]);   // pair @ 4t+2
                u64 H1 = f2u(u2f(QI[ch][1]).y, h2lo1[ch]);   // pair @ 4t+3
                tap4(A3[0], QI[ch][0], k0a, k0b);
                tap4(A3[0], QI[ch][1], k1a, k1b);
                tap4(A3[0], H0,        k2a, k2b);
                tap4(A3[1], QI[ch][1], k0a, k0b);
                tap4(A3[1], H0,        k1a, k1b);
                tap4(A3[1], H1,        k2a, k2b);
            }
            const int p = 4*tid;
            const bool v0 = (p     < 1021), v2 = (p + 2 < 1021);
            const bool v1 = (p + 1 < 1021), v3 = (p + 3 < 1021);
            #pragma unroll
            for (int o = 0; o < 4; o++) {
                float2 r0 = u2f(A3[0][o]);
                float2 r1 = u2f(A3[1][o]);
                psum[4*h+o] += (v0 ? fmaxf(r0.x,0.f) : 0.f) + (v2 ? fmaxf(r0.y,0.f) : 0.f)
                             + (v1 ? fmaxf(r1.x,0.f) : 0.f) + (v3 ? fmaxf(r1.y,0.f) : 0.f);
            }
        }

        // ---- warp reduce -> red[net][warp][oc]; NO barrier, head deferred ----
        #pragma unroll
        for (int oc = 0; oc < 8; oc++) {
            float s = psum[oc];
            #pragma unroll
            for (int off = 16; off > 0; off >>= 1)
                s += __shfl_down_sync(0xFFFFFFFFu, s, off);
            if (lane == 0) red[dn*64 + warp*8 + oc] = s;
        }
        // red hazard: slot dn written once; read only after final barrier.
    }
    __syncthreads();   // final: all red slots visible

    // ---- deferred head, parallel across warps: warp w handles net w ----
    if (warp < nets) {
        const int d = base_net + warp;
        float s = red[warp*64 + lane] + red[warp*64 + 32 + lane];
        s += __shfl_xor_sync(0xFFFFFFFFu, s, 8);
        s += __shfl_xor_sync(0xFFFFFFFFu, s, 16);
        float pj[8];
        #pragma unroll
        for (int j = 0; j < 8; j++)
            pj[j] = __shfl_sync(0xFFFFFFFFu, s, j);
        if (lane < CV) {
            float v = 0.f;
            #pragma unroll
            for (int j = 0; j < 8; j++)
                v = fmaf(pj[j], cWh[(d*CV + lane)*8 + j], v);
            oacc = fmaf(v, cZ[d] * (1.0f/1021.0f), oacc);
        }
    }
    if (warp < nets && lane < CV)
        atomicAdd(&out[b*CV + lane], oacc);
}

extern "C" void kernel_launch(void* const* d_in, const int* in_sizes, int n_in,
                              void* d_out, int out_size) {
    const int*   ids  = (const int*)  d_in[0];
    const float* mask = (const float*)d_in[1];
    const float* z    = (const float*)d_in[2];
    const float* emb  = (const float*)d_in[3];
    const float* W1   = (const float*)d_in[4];
    const float* b1   = (const float*)d_in[5];
    const float* W2   = (const float*)d_in[6];
    const float* b2   = (const float*)d_in[7];
    const float* W3   = (const float*)d_in[8];
    const float* b3   = (const float*)d_in[9];
    const float* Wh   = (const float*)d_in[10];
    const float* bh   = (const float*)d_in[11];
    float* out = (float*)d_out;

    cudaMemcpyToSymbolAsync(cWh, Wh, DZV*80*sizeof(float), 0, cudaMemcpyDeviceToDevice, 0);
    cudaMemcpyToSymbolAsync(cZ,  z,  DZV*sizeof(float),    0, cudaMemcpyDeviceToDevice, 0);

    prep_kernel<<<(DZV*404 + 255)/256, 256>>>(W1, b1, W2, b2, W3, b3, z, bh, out);

    cudaFuncSetAttribute(ensemble_kernel,
                         cudaFuncAttributeMaxDynamicSharedMemorySize,
                         SMEM_FLOATS * (int)sizeof(float));
    ensemble_kernel<<<dim3(B_TOT, 6), NT, SMEM_FLOATS * (int)sizeof(float)>>>(ids, mask, emb, out);
}

// round 16
// speedup vs baseline: 1.1139x; 1.1139x over previous
#include <cuda_runtime.h>
#include <cuda_fp16.h>

#define NT 256
#define L_IN 4096
#define DZV 30
#define CV 10
#define B_TOT 512

typedef unsigned long long u64;

__constant__ float cWh[DZV*80];   // [d][c][j]
__constant__ float cZ[DZV];

// per-net block of 408 u64, all weights pre-duplicated (w,w):
// [0..96)    conv1: ch*12 + k*4 + oc      (ch<8, k<3, oc<4)
// [96..192)  conv2: 96 + ch*24 + k*8 + oc (ch<4, k<3, oc<8)
// [192..384) conv3: 192 + ch*24 + k*8 + oc (ch<8)
// [384..388) b1d, [388..396) b2d, [396..404) b3d, pad 408
__device__ u64 g_wdup[DZV*408];

__device__ __forceinline__ u64 f2u(float a, float b) {
    union { float2 f; u64 u; } c; c.f = make_float2(a, b); return c.u;
}
__device__ __forceinline__ float2 u2f(u64 v) {
    union { float2 f; u64 u; } c; c.u = v; return c.f;
}
__device__ __forceinline__ u64 ffma2(u64 a, u64 b, u64 c) {
    u64 d; asm("fma.rn.f32x2 %0, %1, %2, %3;" : "=l"(d) : "l"(a), "l"(b), "l"(c)); return d;
}
__device__ __forceinline__ void tap4(u64* acc, u64 t, ulonglong2 wa, ulonglong2 wb) {
    acc[0] = ffma2(wa.x, t, acc[0]);
    acc[1] = ffma2(wa.y, t, acc[1]);
    acc[2] = ffma2(wb.x, t, acc[2]);
    acc[3] = ffma2(wb.y, t, acc[3]);
}
__device__ __forceinline__ void tap8(u64* acc, u64 t, const ulonglong2* w4) {
    acc[0] = ffma2(w4[0].x, t, acc[0]);
    acc[1] = ffma2(w4[0].y, t, acc[1]);
    acc[2] = ffma2(w4[1].x, t, acc[2]);
    acc[3] = ffma2(w4[1].y, t, acc[3]);
    acc[4] = ffma2(w4[2].x, t, acc[4]);
    acc[5] = ffma2(w4[2].y, t, acc[5]);
    acc[6] = ffma2(w4[3].x, t, acc[6]);
    acc[7] = ffma2(w4[3].y, t, acc[7]);
}

__global__ void prep_kernel(const float* __restrict__ W1, const float* __restrict__ b1,
                            const float* __restrict__ W2, const float* __restrict__ b2,
                            const float* __restrict__ W3, const float* __restrict__ b3,
                            const float* __restrict__ z,  const float* __restrict__ bh,
                            float* __restrict__ out) {
    int i = blockIdx.x * blockDim.x + threadIdx.x;
    if (i < DZV*404) {
        int n = i / 404, r = i % 404;
        float v;
        if (r < 96) {
            int ch = r / 12, k = (r % 12) / 4, oc = r & 3;
            v = W1[n*96 + oc*24 + ch*3 + k];
        } else if (r < 192) {
            int t = r - 96, ch = t / 24, k = (t % 24) / 8, oc = t & 7;
            v = W2[n*96 + oc*12 + ch*3 + k];
        } else if (r < 384) {
            int t = r - 192, ch = t / 24, k = (t % 24) / 8, oc = t & 7;
            v = W3[n*192 + oc*24 + ch*3 + k];
        } else if (r < 388) v = b1[n*4 + (r-384)];
        else if (r < 396)   v = b2[n*8 + (r-388)];
        else                v = b3[n*8 + (r-396)];
        g_wdup[n*408 + r] = f2u(v, v);
    }
    if (i < B_TOT*CV) {
        int c = i % CV;
        float s = 0.f;
        #pragma unroll
        for (int d = 0; d < DZV; d++) s = fmaf(z[d], bh[d*CV + c], s);
        out[i] = s;
    }
}

// ---- smem layout ----
// XS (fp16): x[pos] at half index ch*CH_STR + (pos&7)*C_STR + (pos>>3)
#define C_STR    516
#define CH_STR   (8*C_STR)    // 4128 halfs
#define RED_OFF  16512        // 15 nets x 64 floats = 960
#define HAL2_OFF 17472        // 2 parities x 8 warps x 16 = 256
#define WS_OFF   17728        // 3 x 816 floats (16B aligned: 17728*4 % 16 == 0)
#define SMEM_FLOATS 20176     // 80704 B -> 2 CTAs/SM

__global__ __launch_bounds__(NT, 2)
void ensemble_kernel(const int* __restrict__ ids,
                     const float* __restrict__ mask,
                     const float* __restrict__ embed,
                     float* __restrict__ out)
{
    extern __shared__ float sm[];
    __half* smh = (__half*)sm;
    float* red  = sm + RED_OFF;
    float* hal2 = sm + HAL2_OFF;

    const int tid  = threadIdx.x;
    const int lane = tid & 31;
    const int warp = tid >> 5;
    const int b    = blockIdx.x;
    const int g    = blockIdx.y;
    const int base_net = g * 15;
    const int nets     = 15;

    // ---- zero pads XS[ch][c][512..515] (one slot per thread) ----
    {
        int ch = tid >> 5, c = (tid >> 2) & 7, j = tid & 3;
        smh[ch*CH_STR + c*C_STR + 512 + j] = __float2half_rn(0.f);
    }

    // ---- stage net base_net's weight block into buffer 0 ----
    if (tid < 204)
        ((float4*)(sm + WS_OFF))[tid] =
            __ldg((const float4*)g_wdup + (size_t)base_net*204 + tid);

    // ---- gather masked embeddings -> fp16, mod-8 deinterleaved ----
    #pragma unroll 1
    for (int i = tid; i < L_IN; i += NT) {
        int   id = __ldg(&ids[b*L_IN + i]);
        float m  = __ldg(&mask[b*L_IN + i]);
        float4 e0 = __ldg((const float4*)(embed + (size_t)id*8));
        float4 e1 = __ldg((const float4*)(embed + (size_t)id*8 + 4));
        __half* bp = smh + (i & 7)*C_STR + (i >> 3);
        bp[0*CH_STR] = __float2half_rn(e0.x*m);
        bp[1*CH_STR] = __float2half_rn(e0.y*m);
        bp[2*CH_STR] = __float2half_rn(e0.z*m);
        bp[3*CH_STR] = __float2half_rn(e0.w*m);
        bp[4*CH_STR] = __float2half_rn(e1.x*m);
        bp[5*CH_STR] = __float2half_rn(e1.y*m);
        bp[6*CH_STR] = __float2half_rn(e1.z*m);
        bp[7*CH_STR] = __float2half_rn(e1.w*m);
    }
    __syncthreads();

    float oacc = 0.f;
    int bcur = 0;   // weight buffer index = dn % 3

    #pragma unroll 1
    for (int dn = 0; dn < nets; dn++) {
        const int d = base_net + dn;
        const ulonglong2* WQ = (const ulonglong2*)(sm + WS_OFF + bcur*816);
        const int bnxt = (bcur == 2) ? 0 : bcur + 1;

        // ---- prefetch net dn+1's weights into buffer (dn+1)%3.
        // 3-deep rotation: concurrent readers (slowest thread in net dn-1's
        // conv3 uses (dn-1)%3; this net uses dn%3) never touch (dn+1)%3.
        if (dn + 1 < nets && tid < 204)
            ((float4*)(sm + WS_OFF + bnxt*816))[tid] =
                __ldg((const float4*)g_wdup + (size_t)(d+1)*204 + tid);

        // ======== conv1: K3 S2, 8->4ch. thread owns r = 8t..8t+7 as
        //          pairs PJ[oc][j] = (h1[8t+j], h1[8t+4+j]), j<4,
        //          PLUS scalar halo h1[8t+8] (recomputed locally) ========
        u64 A1[4][4];   // [j][oc]
        float ax[4];    // scalar accumulators for h1[8t+8]
        {
            ulonglong2 B0 = WQ[192], B1q = WQ[193];
            #pragma unroll
            for (int j = 0; j < 4; j++) {
                A1[j][0] = B0.x; A1[j][1] = B0.y;
                A1[j][2] = B1q.x; A1[j][3] = B1q.y;
            }
            ax[0] = u2f(B0.x).x;  ax[1] = u2f(B0.y).x;
            ax[2] = u2f(B1q.x).x; ax[3] = u2f(B1q.y).x;
        }
        #pragma unroll 2
        for (int ch = 0; ch < 8; ch++) {
            const __half2* Xc = ((const __half2*)smh) + ch*(CH_STR/2) + tid;
            float2 F[8];
            #pragma unroll
            for (int m = 0; m < 8; m++)
                F[m] = __half22float2(Xc[m*(C_STR/2)]);
            float2 Fe = __half22float2(Xc[1]);                // (x[16t+16], x[16t+24])
            float  xb = __half2float(__low2half(Xc[(C_STR/2) + 1]));   // x[16t+17]
            float  xc = __half2float(__low2half(Xc[2*(C_STR/2) + 1])); // x[16t+18]
            u64 P[9];
            #pragma unroll
            for (int m = 0; m < 8; m++) P[m] = f2u(F[m].x, F[m].y);
            P[8] = f2u(F[0].y, Fe.x);
            ulonglong2 w00 = WQ[ch*6+0], w01 = WQ[ch*6+1];
            ulonglong2 w10 = WQ[ch*6+2], w11 = WQ[ch*6+3];
            ulonglong2 w20 = WQ[ch*6+4], w21 = WQ[ch*6+5];
            #pragma unroll
            for (int j = 0; j < 4; j++) {
                tap4(A1[j], P[2*j+0], w00, w01);
                tap4(A1[j], P[2*j+1], w10, w11);
                tap4(A1[j], P[2*j+2], w20, w21);
            }
            // scalar halo r = 8t+8: taps x[16t+16], x[16t+17], x[16t+18]
            ax[0] = fmaf(u2f(w00.x).x, Fe.x, ax[0]);
            ax[1] = fmaf(u2f(w00.y).x, Fe.x, ax[1]);
            ax[2] = fmaf(u2f(w01.x).x, Fe.x, ax[2]);
            ax[3] = fmaf(u2f(w01.y).x, Fe.x, ax[3]);
            ax[0] = fmaf(u2f(w10.x).x, xb, ax[0]);
            ax[1] = fmaf(u2f(w10.y).x, xb, ax[1]);
            ax[2] = fmaf(u2f(w11.x).x, xb, ax[2]);
            ax[3] = fmaf(u2f(w11.y).x, xb, ax[3]);
            ax[0] = fmaf(u2f(w20.x).x, xc, ax[0]);
            ax[1] = fmaf(u2f(w20.y).x, xc, ax[1]);
            ax[2] = fmaf(u2f(w21.x).x, xc, ax[2]);
            ax[3] = fmaf(u2f(w21.y).x, xc, ax[3]);
        }
        // ReLU -> PJ pairs + h1x halo, all register-resident (no barrier!)
        u64 PJ[4][4];
        float h1x[4];
        #pragma unroll
        for (int oc = 0; oc < 4; oc++) {
            #pragma unroll
            for (int j = 0; j < 4; j++) {
                float2 p = u2f(A1[j][oc]);
                PJ[oc][j] = f2u(fmaxf(p.x, 0.f), fmaxf(p.y, 0.f));
            }
            h1x[oc] = fmaxf(ax[oc], 0.f);
        }

        // ======== conv2: K3 S2, 4->8ch. q = 4t..4t+3 as
        //          pairs QI[oc][i] = (h2[4t+i], h2[4t+2+i]), i<2 ========
        u64 A2[2][8];
        {
            ulonglong2 B0 = WQ[194], B1q = WQ[195], B2q = WQ[196], B3q = WQ[197];
            #pragma unroll
            for (int i = 0; i < 2; i++) {
                A2[i][0]=B0.x;  A2[i][1]=B0.y;  A2[i][2]=B1q.x; A2[i][3]=B1q.y;
                A2[i][4]=B2q.x; A2[i][5]=B2q.y; A2[i][6]=B3q.x; A2[i][7]=B3q.y;
            }
        }
        #pragma unroll
        for (int ch = 0; ch < 4; ch++) {
            const ulonglong2* wp = WQ + 48 + ch*12;
            ulonglong2 w0[4], w1[4], w2[4];
            #pragma unroll
            for (int j = 0; j < 4; j++) { w0[j]=wp[j]; w1[j]=wp[4+j]; w2[j]=wp[8+j]; }
            u64 HX = f2u(u2f(PJ[ch][0]).y, h1x[ch]);   // h1 pair (8t+4, 8t+8)
            tap8(A2[0], PJ[ch][0], w0);
            tap8(A2[0], PJ[ch][1], w1);
            tap8(A2[0], PJ[ch][2], w2);
            tap8(A2[1], PJ[ch][2], w0);
            tap8(A2[1], PJ[ch][3], w1);
            tap8(A2[1], HX,        w2);
        }
        // ReLU -> QI[oc][i]: stride-2 h2 pairs
        u64 QI[8][2];
        #pragma unroll
        for (int oc = 0; oc < 8; oc++)
            #pragma unroll
            for (int i = 0; i < 2; i++) {
                float2 p = u2f(A2[i][oc]);
                QI[oc][i] = f2u(fmaxf(p.x, 0.f), fmaxf(p.y, 0.f));
            }

        // ---- h2 halo post (net-parity buffer) + the ONLY barrier this net ----
        float* h2b = hal2 + (dn & 1)*128;
        if (lane == 0) {
            #pragma unroll
            for (int ch = 0; ch < 8; ch++) {
                h2b[warp*16 + ch]     = u2f(QI[ch][0]).x;
                h2b[warp*16 + 8 + ch] = u2f(QI[ch][1]).x;
            }
        }
        __syncthreads();                                  // B (one per net)

        float h2lo0[8], h2lo1[8];
        #pragma unroll
        for (int ch = 0; ch < 8; ch++) {
            h2lo0[ch] = __shfl_down_sync(0xFFFFFFFFu, u2f(QI[ch][0]).x, 1);
            h2lo1[ch] = __shfl_down_sync(0xFFFFFFFFu, u2f(QI[ch][1]).x, 1);
        }
        if (lane == 31 && warp < 7) {
            #pragma unroll
            for (int ch = 0; ch < 8; ch++) {
                h2lo0[ch] = h2b[(warp+1)*16 + ch];
                h2lo1[ch] = h2b[(warp+1)*16 + 8 + ch];
            }
        }
        // t=255: halo garbage -> feeds only p>=1021, masked in the pool.

        // ======== conv3: K3 S1, 8->8ch, ReLU + pool.
        //          pairs (4t, 4t+2) and (4t+1, 4t+3); valid p < 1021 ========
        float psum[8];
        #pragma unroll
        for (int i = 0; i < 8; i++) psum[i] = 0.f;
        {
            u64 A3[2][8];
            {
                ulonglong2 B0 = WQ[198], B1q = WQ[199], B2q = WQ[200], B3q = WQ[201];
                #pragma unroll
                for (int i = 0; i < 2; i++) {
                    A3[i][0]=B0.x;  A3[i][1]=B0.y;  A3[i][2]=B1q.x; A3[i][3]=B1q.y;
                    A3[i][4]=B2q.x; A3[i][5]=B2q.y; A3[i][6]=B3q.x; A3[i][7]=B3q.y;
                }
            }
            #pragma unroll 2
            for (int ch = 0; ch < 8; ch++) {
                const ulonglong2* wp = WQ + 96 + ch*12;
                ulonglong2 w0[4], w1[4], w2[4];
                #pragma unroll
                for (int j = 0; j < 4; j++) { w0[j]=wp[j]; w1[j]=wp[4+j]; w2[j]=wp[8+j]; }
                u64 H0 = f2u(u2f(QI[ch][0]).y, h2lo0[ch]);  // pair @ 4t+2
                u64 H1 = f2u(u2f(QI[ch][1]).y, h2lo1[ch]);  // pair @ 4t+3
                tap8(A3[0], QI[ch][0], w0);
                tap8(A3[0], QI[ch][1], w1);
                tap8(A3[0], H0,        w2);
                tap8(A3[1], QI[ch][1], w0);
                tap8(A3[1], H0,        w1);
                tap8(A3[1], H1,        w2);
            }
            const int p = 4*tid;
            const bool v0 = (p     < 1021);
            const bool v2 = (p + 2 < 1021);
            const bool v1 = (p + 1 < 1021);
            const bool v3 = (p + 3 < 1021);
            #pragma unroll
            for (int oc = 0; oc < 8; oc++) {
                float2 r0 = u2f(A3[0][oc]);
                float2 r1 = u2f(A3[1][oc]);
                psum[oc] += (v0 ? fmaxf(r0.x,0.f) : 0.f) + (v2 ? fmaxf(r0.y,0.f) : 0.f)
                          + (v1 ? fmaxf(r1.x,0.f) : 0.f) + (v3 ? fmaxf(r1.y,0.f) : 0.f);
            }
        }

        // ---- warp reduce -> red[net][warp][oc]; NO barrier, head deferred ----
        #pragma unroll
        for (int oc = 0; oc < 8; oc++) {
            float s = psum[oc];
            #pragma unroll
            for (int off = 16; off > 0; off >>= 1)
                s += __shfl_down_sync(0xFFFFFFFFu, s, off);
            if (lane == 0) red[dn*64 + warp*8 + oc] = s;
        }
        // red slot dn written once; read only after final barrier.

        bcur = bnxt;
    }
    __syncthreads();   // final: all red slots visible

    // ---- deferred head, parallel across warps: warp w handles nets w, w+8 ----
    #pragma unroll 1
    for (int nn = warp; nn < nets; nn += 8) {
        const int d = base_net + nn;
        float s = red[nn*64 + lane] + red[nn*64 + 32 + lane];
        s += __shfl_xor_sync(0xFFFFFFFFu, s, 8);
        s += __shfl_xor_sync(0xFFFFFFFFu, s, 16);
        float pj[8];
        #pragma unroll
        for (int j = 0; j < 8; j++)
            pj[j] = __shfl_sync(0xFFFFFFFFu, s, j);
        if (lane < CV) {
            float v = 0.f;
            #pragma unroll
            for (int j = 0; j < 8; j++)
                v = fmaf(pj[j], cWh[(d*CV + lane)*8 + j], v);
            oacc = fmaf(v, cZ[d] * (1.0f/1021.0f), oacc);
        }
    }
    if (lane < CV)
        atomicAdd(&out[b*CV + lane], oacc);
}

extern "C" void kernel_launch(void* const* d_in, const int* in_sizes, int n_in,
                              void* d_out, int out_size) {
    const int*   ids  = (const int*)  d_in[0];
    const float* mask = (const float*)d_in[1];
    const float* z    = (const float*)d_in[2];
    const float* emb  = (const float*)d_in[3];
    const float* W1   = (const float*)d_in[4];
    const float* b1   = (const float*)d_in[5];
    const float* W2   = (const float*)d_in[6];
    const float* b2   = (const float*)d_in[7];
    const float* W3   = (const float*)d_in[8];
    const float* b3   = (const float*)d_in[9];
    const float* Wh   = (const float*)d_in[10];
    const float* bh   = (const float*)d_in[11];
    float* out = (float*)d_out;

    cudaMemcpyToSymbolAsync(cWh, Wh, DZV*80*sizeof(float), 0, cudaMemcpyDeviceToDevice, 0);
    cudaMemcpyToSymbolAsync(cZ,  z,  DZV*sizeof(float),    0, cudaMemcpyDeviceToDevice, 0);

    prep_kernel<<<(DZV*404 + 255)/256, 256>>>(W1, b1, W2, b2, W3, b3, z, bh, out);

    cudaFuncSetAttribute(ensemble_kernel,
                         cudaFuncAttributeMaxDynamicSharedMemorySize,
                         SMEM_FLOATS * (int)sizeof(float));
    ensemble_kernel<<<dim3(B_TOT, 2), NT, SMEM_FLOATS * (int)sizeof(float)>>>(ids, mask, emb, out);
}